// round 15
// baseline (speedup 1.0000x reference)
#include <cuda_runtime.h>
#include <math.h>
#include <stdint.h>

#define DM 256
#define NH 4
#define HD 64
#define NN 768
#define MM 768

#define TILE_M 16
#define NBUF 3
#define NT (MM / TILE_M)              // 48 tiles
#define TILE_BYTES (TILE_M * DM * 4)  // 16384
#define TILE_FLOATS (TILE_M * DM)     // 4096
#define DYN_SMEM_BYTES ((NH * MM + NBUF * TILE_FLOATS) * 4)   // 61440

// ---- scratch (static device globals: allocation-free) ----
__device__ float g_q[NN * DM];
__device__ float g_k[NN * DM];            // k' = 0.125*(xk@Wk.T + bk + bp)
__device__ float g_v[NN * DM];
__device__ float g_R[NN * NH * DM];       // R[n][h][e] = 0.125 * q_h[n] @ Wp_h
__device__ float g_Se[NH * NN * MM];      // q·k' (scaled, bp folded)

// ---- mbarrier / bulk-copy PTX helpers ----
__device__ __forceinline__ uint32_t smem_u32(const void* p) {
    return (uint32_t)__cvta_generic_to_shared(p);
}
#define MB_INIT(addr, cnt) \
    asm volatile("mbarrier.init.shared.b64 [%0], %1;" :: "r"(addr), "r"(cnt) : "memory")
#define MB_EXPECT_TX(addr, bytes) \
    asm volatile("mbarrier.arrive.expect_tx.shared.b64 _, [%0], %1;" :: "r"(addr), "r"(bytes) : "memory")
#define MB_ARRIVE(addr) \
    asm volatile("mbarrier.arrive.shared.b64 _, [%0];" :: "r"(addr) : "memory")
#define BULK_G2S(dst, src, bytes, mbar_) \
    asm volatile("cp.async.bulk.shared::cluster.global.mbarrier::complete_tx::bytes [%0], [%1], %2, [%3];" \
                 :: "r"(dst), "l"(src), "r"(bytes), "r"(mbar_) : "memory")

__device__ __forceinline__ void mbar_wait(uint32_t addr, uint32_t parity) {
    asm volatile(
        "{\n\t"
        ".reg .pred P;\n\t"
        "WL%=:\n\t"
        "mbarrier.try_wait.parity.acquire.cta.shared::cta.b64 P, [%0], %1, 0x989680;\n\t"
        "@P bra WD%=;\n\t"
        "bra WL%=;\n\t"
        "WD%=:\n\t"
        "}"
        :: "r"(addr), "r"(parity) : "memory");
}

// ============================================================
// K1: q/k'/v projections.  grid (48, 3), 256 threads.  (R10 exact)
// ============================================================
__global__ __launch_bounds__(256) void qkv_kernel(
    const float* __restrict__ in_q, const float* __restrict__ in_k, const float* __restrict__ in_v,
    const float* __restrict__ Wq, const float* __restrict__ bq,
    const float* __restrict__ Wk, const float* __restrict__ bk,
    const float* __restrict__ Wv, const float* __restrict__ bv,
    const float* __restrict__ bp)
{
    const int z  = blockIdx.y;
    const int n0 = blockIdx.x * 16;
    const int d  = threadIdx.x;

    const float* x = (z == 0) ? in_q : ((z == 1) ? in_k : in_v);
    const float* W = (z == 0) ? Wq   : ((z == 1) ? Wk   : Wv);
    float bias     = (z == 0) ? bq[d] : ((z == 1) ? (bk[d] + bp[d]) : bv[d]);
    const float scale = (z == 1) ? 0.125f : 1.0f;
    float* out = (z == 0) ? g_q : ((z == 1) ? g_k : g_v);

    __shared__ float xs[256 * 20];
    for (int idx = d; idx < 16 * 256; idx += 256) {
        int ni = idx >> 8, e = idx & 255;
        xs[e * 20 + ni] = x[(n0 + ni) * DM + e];
    }
    __syncthreads();

    float4 acc[4];
    #pragma unroll
    for (int g = 0; g < 4; g++) acc[g] = make_float4(0.f, 0.f, 0.f, 0.f);

    const float4* Wr = (const float4*)(W + d * DM);
    #pragma unroll 4
    for (int e4 = 0; e4 < 64; e4++) {
        float4 wv = Wr[e4];
        float wa[4] = {wv.x, wv.y, wv.z, wv.w};
        #pragma unroll
        for (int k = 0; k < 4; k++) {
            int e = e4 * 4 + k;
            float w = wa[k];
            #pragma unroll
            for (int g = 0; g < 4; g++) {
                float4 xf = *(const float4*)&xs[e * 20 + g * 4];
                acc[g].x += xf.x * w;
                acc[g].y += xf.y * w;
                acc[g].z += xf.z * w;
                acc[g].w += xf.w * w;
            }
        }
    }
    #pragma unroll
    for (int g = 0; g < 4; g++) {
        out[(n0 + g * 4 + 0) * DM + d] = scale * (acc[g].x + bias);
        out[(n0 + g * 4 + 1) * DM + d] = scale * (acc[g].y + bias);
        out[(n0 + g * 4 + 2) * DM + d] = scale * (acc[g].z + bias);
        out[(n0 + g * 4 + 3) * DM + d] = scale * (acc[g].w + bias);
    }
}

// ============================================================
// K2: R projection.  grid (48, 4), 256 threads.  (R10 exact)
// ============================================================
__global__ __launch_bounds__(256) void rproj_kernel(const float* __restrict__ Wp)
{
    const int n0 = blockIdx.x * 16;
    const int h  = blockIdx.y;
    const int e  = threadIdx.x;

    __shared__ float qs[64 * 20];
    for (int idx = e; idx < 16 * 64; idx += 256) {
        int ni = idx >> 6, c = idx & 63;
        qs[c * 20 + ni] = g_q[(n0 + ni) * DM + h * 64 + c];
    }
    __syncthreads();

    float4 acc[4];
    #pragma unroll
    for (int g = 0; g < 4; g++) acc[g] = make_float4(0.f, 0.f, 0.f, 0.f);

    #pragma unroll 4
    for (int c = 0; c < 64; c++) {
        float w = Wp[(h * 64 + c) * DM + e];
        #pragma unroll
        for (int g = 0; g < 4; g++) {
            float4 xf = *(const float4*)&qs[c * 20 + g * 4];
            acc[g].x += xf.x * w;
            acc[g].y += xf.y * w;
            acc[g].z += xf.z * w;
            acc[g].w += xf.w * w;
        }
    }
    #pragma unroll
    for (int g = 0; g < 4; g++) {
        g_R[(n0 + g * 4 + 0) * (NH * DM) + h * DM + e] = 0.125f * acc[g].x;
        g_R[(n0 + g * 4 + 1) * (NH * DM) + h * DM + e] = 0.125f * acc[g].y;
        g_R[(n0 + g * 4 + 2) * (NH * DM) + h * DM + e] = 0.125f * acc[g].z;
        g_R[(n0 + g * 4 + 3) * (NH * DM) + h * DM + e] = 0.125f * acc[g].w;
    }
}

// ============================================================
// K3: Se[h][n][m] = q_h[n] · k'_h[m].   grid (12, 12, 4), 256 threads.
// ============================================================
__global__ __launch_bounds__(256) void se_kernel()
{
    const int m0 = blockIdx.x * 64;
    const int n0 = blockIdx.y * 64;
    const int h  = blockIdx.z;
    const int tid = threadIdx.x;

    __shared__ float qs[64 * 68];
    __shared__ float ks[64 * 68];
    for (int idx = tid; idx < 64 * 64; idx += 256) {
        int i = idx >> 6, c = idx & 63;
        qs[c * 68 + i] = g_q[(n0 + i) * DM + h * 64 + c];
        ks[c * 68 + i] = g_k[(m0 + i) * DM + h * 64 + c];
    }
    __syncthreads();

    const int tx = tid & 15, ty = tid >> 4;
    float acc[4][4];
    #pragma unroll
    for (int i = 0; i < 4; i++)
        #pragma unroll
        for (int j = 0; j < 4; j++) acc[i][j] = 0.f;

    #pragma unroll 4
    for (int c = 0; c < 64; c++) {
        float4 a = *(const float4*)&qs[c * 68 + ty * 4];
        float4 b = *(const float4*)&ks[c * 68 + tx * 4];
        float av[4] = {a.x, a.y, a.z, a.w};
        float bv[4] = {b.x, b.y, b.z, b.w};
        #pragma unroll
        for (int i = 0; i < 4; i++)
            #pragma unroll
            for (int j = 0; j < 4; j++) acc[i][j] += av[i] * bv[j];
    }
    #pragma unroll
    for (int i = 0; i < 4; i++) {
        float4 r = make_float4(acc[i][0], acc[i][1], acc[i][2], acc[i][3]);
        *(float4*)&g_Se[((size_t)h * NN + (n0 + ty * 4 + i)) * MM + m0 + tx * 4] = r;
    }
}

// ============================================================
// K4: fused RPE-score + softmax, depth-3 bulk-copy pipeline. (R10 exact)
// ============================================================
__global__ __launch_bounds__(256, 3) void attn_kernel(const float* __restrict__ emb,
                                                      float* __restrict__ attn_out)
{
    extern __shared__ __align__(16) float dyn[];
    float* sc  = dyn;                 // NH*MM floats (12 KB)
    float* buf = dyn + NH * MM;       // NBUF * 4096 floats (48 KB)

    const int n    = blockIdx.x;
    const int tid  = threadIdx.x;
    const int lane = tid & 31;
    const int wrp  = tid >> 5;

    __shared__ __align__(8) unsigned long long mbar[2 * NBUF];
    __shared__ float red[8];

    const uint32_t mb   = smem_u32(mbar);
    const uint32_t bufa = smem_u32(buf);

    if (tid == 0) {
        #pragma unroll
        for (int i = 0; i < NBUF; i++) {
            MB_INIT(mb + i * 8, 1);
            MB_INIT(mb + (NBUF + i) * 8, 8);
        }
    }

    #pragma unroll
    for (int h = 0; h < NH; h++)
        for (int m = tid; m < MM; m += 256)
            sc[h * MM + m] = g_Se[((size_t)h * NN + n) * MM + m];

    const float4* Rr = (const float4*)(g_R + (size_t)n * NH * DM);
    float4 rA[NH], rB[NH];
    #pragma unroll
    for (int h = 0; h < NH; h++) {
        rA[h] = Rr[h * 64 + lane];
        rB[h] = Rr[h * 64 + 32 + lane];
    }
    __syncthreads();

    const char* src = (const char*)(emb + (size_t)n * MM * DM);
    if (tid == 0) {
        #pragma unroll
        for (int i = 0; i < NBUF; i++) {
            MB_EXPECT_TX(mb + i * 8, TILE_BYTES);
            BULK_G2S(bufa + i * TILE_BYTES, src + (size_t)i * TILE_BYTES,
                     (uint32_t)TILE_BYTES, mb + i * 8);
        }
    }

    const unsigned F = 0xffffffffu;
    const bool o1 = lane & 1, o2 = lane & 2, o4 = lane & 4;

    int s = 0;
    uint32_t par = 0;
    for (int t = 0; t < NT; t++) {
        const uint32_t fa = mb + s * 8;
        const uint32_t ea = mb + (NBUF + s) * 8;

        mbar_wait(fa, par);

        const float* bufp = buf + s * TILE_FLOATS;
        const float4* r0p = (const float4*)(bufp + (wrp * 2) * DM);
        const float4* r1p = (const float4*)(bufp + (wrp * 2 + 1) * DM);
        float4 a0 = r0p[lane], a1 = r0p[32 + lane];
        float4 b0 = r1p[lane], b1 = r1p[32 + lane];

        float acc0[NH], acc1[NH];
        #pragma unroll
        for (int h = 0; h < NH; h++) {
            acc0[h] = a0.x * rA[h].x + a0.y * rA[h].y + a0.z * rA[h].z + a0.w * rA[h].w
                    + a1.x * rB[h].x + a1.y * rB[h].y + a1.z * rB[h].z + a1.w * rB[h].w;
            acc1[h] = b0.x * rA[h].x + b0.y * rA[h].y + b0.z * rA[h].z + b0.w * rA[h].w
                    + b1.x * rB[h].x + b1.y * rB[h].y + b1.z * rB[h].z + b1.w * rB[h].w;
        }

        float sx, rx;
        sx = o1 ? acc0[0] : acc0[1]; rx = __shfl_xor_sync(F, sx, 1);
        float v01a = (o1 ? acc0[1] : acc0[0]) + rx;
        sx = o1 ? acc0[2] : acc0[3]; rx = __shfl_xor_sync(F, sx, 1);
        float v23a = (o1 ? acc0[3] : acc0[2]) + rx;
        sx = o1 ? acc1[0] : acc1[1]; rx = __shfl_xor_sync(F, sx, 1);
        float v01b = (o1 ? acc1[1] : acc1[0]) + rx;
        sx = o1 ? acc1[2] : acc1[3]; rx = __shfl_xor_sync(F, sx, 1);
        float v23b = (o1 ? acc1[3] : acc1[2]) + rx;

        sx = o2 ? v01a : v23a; rx = __shfl_xor_sync(F, sx, 2);
        float ua = (o2 ? v23a : v01a) + rx;
        sx = o2 ? v01b : v23b; rx = __shfl_xor_sync(F, sx, 2);
        float ub = (o2 ? v23b : v01b) + rx;

        sx = o4 ? ua : ub; rx = __shfl_xor_sync(F, sx, 4);
        float w = (o4 ? ub : ua) + rx;
        w += __shfl_xor_sync(F, w, 8);
        w += __shfl_xor_sync(F, w, 16);

        if (lane < 8)
            sc[(lane & 3) * MM + t * TILE_M + wrp * 2 + ((lane >> 2) & 1)] += w;

        __syncwarp();
        if (lane == 0) MB_ARRIVE(ea);

        if (tid == 0 && t + NBUF < NT) {
            mbar_wait(ea, par);
            MB_EXPECT_TX(fa, TILE_BYTES);
            BULK_G2S(bufa + s * TILE_BYTES, src + (size_t)(t + NBUF) * TILE_BYTES,
                     (uint32_t)TILE_BYTES, fa);
        }

        if (++s == NBUF) { s = 0; par ^= 1; }
    }
    __syncthreads();

    const int h = tid >> 6;
    const int t = tid & 63;

    float mx = -1e30f;
    for (int m = t; m < MM; m += 64) mx = fmaxf(mx, sc[h * MM + m]);
    #pragma unroll
    for (int d = 16; d; d >>= 1) mx = fmaxf(mx, __shfl_xor_sync(0xffffffffu, mx, d));
    if (lane == 0) red[wrp] = mx;
    __syncthreads();
    const float hmax = fmaxf(red[h * 2], red[h * 2 + 1]);

    float sum = 0.f;
    for (int m = t; m < MM; m += 64) {
        float e = __expf(sc[h * MM + m] - hmax);
        sc[h * MM + m] = e;
        sum += e;
    }
    #pragma unroll
    for (int d = 16; d; d >>= 1) sum += __shfl_xor_sync(0xffffffffu, sum, d);
    __syncthreads();
    if (lane == 0) red[wrp] = sum;
    __syncthreads();
    const float inv = 1.0f / (red[h * 2] + red[h * 2 + 1]);

    float* ao = attn_out + ((size_t)h * NN + n) * MM;
    for (int m = t; m < MM; m += 64) ao[m] = sc[h * MM + m] * inv;
}

// ============================================================
// K5: hidden = attn @ v — barrier-free warp-autonomous version.
// grid (48, 4), 256 threads (8 warps). Warp w owns rows n0+2w, n0+2w+1
// for head h; lane owns output cols h*64 + lane*2, +1.
// attn row chunks loaded coalesced into lanes, broadcast via shfl;
// v rows read as coalesced float2 (L1/L2-resident, reused by all warps).
// No smem, no __syncthreads, no atomics.
// ============================================================
__global__ __launch_bounds__(256) void av_kernel(const float* __restrict__ attn_g,
                                                 float* __restrict__ out_h)
{
    const int n0   = blockIdx.x * 16;
    const int h    = blockIdx.y;
    const int tid  = threadIdx.x;
    const int lane = tid & 31;
    const int wid  = tid >> 5;
    const int n    = n0 + wid * 2;

    const unsigned F = 0xffffffffu;
    const float* a0p = attn_g + ((size_t)h * NN + n) * MM;
    const float* a1p = a0p + MM;
    const float* vbase = g_v + h * 64 + lane * 2;

    float2 acc0 = make_float2(0.f, 0.f);
    float2 acc1 = make_float2(0.f, 0.f);

    for (int m0 = 0; m0 < MM; m0 += 32) {
        float a0 = a0p[m0 + lane];
        float a1 = a1p[m0 + lane];
        #pragma unroll
        for (int i = 0; i < 32; i++) {
            float w0 = __shfl_sync(F, a0, i);
            float w1 = __shfl_sync(F, a1, i);
            float2 vv = *(const float2*)(vbase + (size_t)(m0 + i) * DM);
            acc0.x += w0 * vv.x; acc0.y += w0 * vv.y;
            acc1.x += w1 * vv.x; acc1.y += w1 * vv.y;
        }
    }

    float* o0 = out_h + (size_t)n * DM + h * 64 + lane * 2;
    *(float2*)o0 = acc0;
    *(float2*)(o0 + DM) = acc1;
}

// ============================================================
// launch
// ============================================================
extern "C" void kernel_launch(void* const* d_in, const int* in_sizes, int n_in,
                              void* d_out, int out_size)
{
    const float* in_q = (const float*)d_in[0];
    const float* in_k = (const float*)d_in[1];
    const float* in_v = (const float*)d_in[2];
    const float* emb  = (const float*)d_in[3];
    const float* Wq   = (const float*)d_in[4];
    const float* bq   = (const float*)d_in[5];
    const float* Wk   = (const float*)d_in[6];
    const float* bk   = (const float*)d_in[7];
    const float* Wv   = (const float*)d_in[8];
    const float* bv   = (const float*)d_in[9];
    const float* Wp   = (const float*)d_in[10];
    const float* bp   = (const float*)d_in[11];

    float* out      = (float*)d_out;
    float* out_attn = out + NN * DM;   // hidden (196608) then attn (2359296)

    static bool attr_set = false;
    if (!attr_set) {
        cudaFuncSetAttribute(attn_kernel, cudaFuncAttributeMaxDynamicSharedMemorySize,
                             DYN_SMEM_BYTES);
        attr_set = true;
    }

    qkv_kernel<<<dim3(NN / 16, 3), 256>>>(in_q, in_k, in_v, Wq, bq, Wk, bk, Wv, bv, bp);
    rproj_kernel<<<dim3(NN / 16, NH), 256>>>(Wp);
    se_kernel<<<dim3(MM / 64, NN / 64, NH), 256>>>();
    attn_kernel<<<NN, 256, DYN_SMEM_BYTES>>>(emb, out_attn);
    av_kernel<<<dim3(NN / 16, NH), 256>>>(out_attn, out);
}

// round 16
// speedup vs baseline: 1.2040x; 1.2040x over previous
#include <cuda_runtime.h>
#include <math.h>
#include <stdint.h>

#define DM 256
#define NH 4
#define HD 64
#define NN 768
#define MM 768

#define TILE_M 16
#define NBUF 3
#define NT (MM / TILE_M)              // 48 tiles
#define TILE_BYTES (TILE_M * DM * 4)  // 16384
#define TILE_FLOATS (TILE_M * DM)     // 4096
#define DYN_SMEM_BYTES ((NH * MM + NBUF * TILE_FLOATS) * 4)   // 61440

// av kernel: 8 n-rows per block, per stage attn[8][64] + v[64][64]
#define AV_CH 64
#define AV_PH (MM / AV_CH)                            // 12 phases
#define AV_ROWS 8
#define AV_BUF_FLOATS (AV_ROWS * AV_CH + AV_CH * 64)  // 4608
#define AV_DYN_BYTES (3 * AV_BUF_FLOATS * 4)          // 55296

// ---- scratch (static device globals: allocation-free) ----
__device__ float g_q[NN * DM];
__device__ float g_k[NN * DM];            // k' = 0.125*(xk@Wk.T + bk + bp)
__device__ float g_v[NN * DM];
__device__ float g_R[NN * NH * DM];       // R[n][h][e] = 0.125 * q_h[n] @ Wp_h
__device__ float g_Se[NH * NN * MM];      // q·k' (scaled, bp folded)

// ---- mbarrier / bulk-copy / cp.async PTX helpers ----
__device__ __forceinline__ uint32_t smem_u32(const void* p) {
    return (uint32_t)__cvta_generic_to_shared(p);
}
#define MB_INIT(addr, cnt) \
    asm volatile("mbarrier.init.shared.b64 [%0], %1;" :: "r"(addr), "r"(cnt) : "memory")
#define MB_EXPECT_TX(addr, bytes) \
    asm volatile("mbarrier.arrive.expect_tx.shared.b64 _, [%0], %1;" :: "r"(addr), "r"(bytes) : "memory")
#define MB_ARRIVE(addr) \
    asm volatile("mbarrier.arrive.shared.b64 _, [%0];" :: "r"(addr) : "memory")
#define BULK_G2S(dst, src, bytes, mbar_) \
    asm volatile("cp.async.bulk.shared::cluster.global.mbarrier::complete_tx::bytes [%0], [%1], %2, [%3];" \
                 :: "r"(dst), "l"(src), "r"(bytes), "r"(mbar_) : "memory")

__device__ __forceinline__ void mbar_wait(uint32_t addr, uint32_t parity) {
    asm volatile(
        "{\n\t"
        ".reg .pred P;\n\t"
        "WL%=:\n\t"
        "mbarrier.try_wait.parity.acquire.cta.shared::cta.b64 P, [%0], %1, 0x989680;\n\t"
        "@P bra WD%=;\n\t"
        "bra WL%=;\n\t"
        "WD%=:\n\t"
        "}"
        :: "r"(addr), "r"(parity) : "memory");
}

__device__ __forceinline__ void cp_async16(float* dst, const float* src) {
    asm volatile("cp.async.ca.shared.global [%0], [%1], 16;"
                 :: "r"(smem_u32(dst)), "l"(src) : "memory");
}
#define CP_COMMIT() asm volatile("cp.async.commit_group;" ::: "memory")
#define CP_WAIT(n)  asm volatile("cp.async.wait_group %0;" :: "n"(n) : "memory")

// ============================================================
// K1: q/k'/v projections.  grid (48, 3), 256 threads.  (R10 exact)
// ============================================================
__global__ __launch_bounds__(256) void qkv_kernel(
    const float* __restrict__ in_q, const float* __restrict__ in_k, const float* __restrict__ in_v,
    const float* __restrict__ Wq, const float* __restrict__ bq,
    const float* __restrict__ Wk, const float* __restrict__ bk,
    const float* __restrict__ Wv, const float* __restrict__ bv,
    const float* __restrict__ bp)
{
    const int z  = blockIdx.y;
    const int n0 = blockIdx.x * 16;
    const int d  = threadIdx.x;

    const float* x = (z == 0) ? in_q : ((z == 1) ? in_k : in_v);
    const float* W = (z == 0) ? Wq   : ((z == 1) ? Wk   : Wv);
    float bias     = (z == 0) ? bq[d] : ((z == 1) ? (bk[d] + bp[d]) : bv[d]);
    const float scale = (z == 1) ? 0.125f : 1.0f;
    float* out = (z == 0) ? g_q : ((z == 1) ? g_k : g_v);

    __shared__ float xs[256 * 20];
    for (int idx = d; idx < 16 * 256; idx += 256) {
        int ni = idx >> 8, e = idx & 255;
        xs[e * 20 + ni] = x[(n0 + ni) * DM + e];
    }
    __syncthreads();

    float4 acc[4];
    #pragma unroll
    for (int g = 0; g < 4; g++) acc[g] = make_float4(0.f, 0.f, 0.f, 0.f);

    const float4* Wr = (const float4*)(W + d * DM);
    #pragma unroll 4
    for (int e4 = 0; e4 < 64; e4++) {
        float4 wv = Wr[e4];
        float wa[4] = {wv.x, wv.y, wv.z, wv.w};
        #pragma unroll
        for (int k = 0; k < 4; k++) {
            int e = e4 * 4 + k;
            float w = wa[k];
            #pragma unroll
            for (int g = 0; g < 4; g++) {
                float4 xf = *(const float4*)&xs[e * 20 + g * 4];
                acc[g].x += xf.x * w;
                acc[g].y += xf.y * w;
                acc[g].z += xf.z * w;
                acc[g].w += xf.w * w;
            }
        }
    }
    #pragma unroll
    for (int g = 0; g < 4; g++) {
        out[(n0 + g * 4 + 0) * DM + d] = scale * (acc[g].x + bias);
        out[(n0 + g * 4 + 1) * DM + d] = scale * (acc[g].y + bias);
        out[(n0 + g * 4 + 2) * DM + d] = scale * (acc[g].z + bias);
        out[(n0 + g * 4 + 3) * DM + d] = scale * (acc[g].w + bias);
    }
}

// ============================================================
// K2: R projection.  grid (48, 4), 256 threads.  (R10 exact)
// ============================================================
__global__ __launch_bounds__(256) void rproj_kernel(const float* __restrict__ Wp)
{
    const int n0 = blockIdx.x * 16;
    const int h  = blockIdx.y;
    const int e  = threadIdx.x;

    __shared__ float qs[64 * 20];
    for (int idx = e; idx < 16 * 64; idx += 256) {
        int ni = idx >> 6, c = idx & 63;
        qs[c * 20 + ni] = g_q[(n0 + ni) * DM + h * 64 + c];
    }
    __syncthreads();

    float4 acc[4];
    #pragma unroll
    for (int g = 0; g < 4; g++) acc[g] = make_float4(0.f, 0.f, 0.f, 0.f);

    #pragma unroll 4
    for (int c = 0; c < 64; c++) {
        float w = Wp[(h * 64 + c) * DM + e];
        #pragma unroll
        for (int g = 0; g < 4; g++) {
            float4 xf = *(const float4*)&qs[c * 20 + g * 4];
            acc[g].x += xf.x * w;
            acc[g].y += xf.y * w;
            acc[g].z += xf.z * w;
            acc[g].w += xf.w * w;
        }
    }
    #pragma unroll
    for (int g = 0; g < 4; g++) {
        g_R[(n0 + g * 4 + 0) * (NH * DM) + h * DM + e] = 0.125f * acc[g].x;
        g_R[(n0 + g * 4 + 1) * (NH * DM) + h * DM + e] = 0.125f * acc[g].y;
        g_R[(n0 + g * 4 + 2) * (NH * DM) + h * DM + e] = 0.125f * acc[g].z;
        g_R[(n0 + g * 4 + 3) * (NH * DM) + h * DM + e] = 0.125f * acc[g].w;
    }
}

// ============================================================
// K3: Se[h][n][m] = q_h[n] · k'_h[m].   grid (12, 12, 4), 256 threads.
// ============================================================
__global__ __launch_bounds__(256) void se_kernel()
{
    const int m0 = blockIdx.x * 64;
    const int n0 = blockIdx.y * 64;
    const int h  = blockIdx.z;
    const int tid = threadIdx.x;

    __shared__ float qs[64 * 68];
    __shared__ float ks[64 * 68];
    for (int idx = tid; idx < 64 * 64; idx += 256) {
        int i = idx >> 6, c = idx & 63;
        qs[c * 68 + i] = g_q[(n0 + i) * DM + h * 64 + c];
        ks[c * 68 + i] = g_k[(m0 + i) * DM + h * 64 + c];
    }
    __syncthreads();

    const int tx = tid & 15, ty = tid >> 4;
    float acc[4][4];
    #pragma unroll
    for (int i = 0; i < 4; i++)
        #pragma unroll
        for (int j = 0; j < 4; j++) acc[i][j] = 0.f;

    #pragma unroll 4
    for (int c = 0; c < 64; c++) {
        float4 a = *(const float4*)&qs[c * 68 + ty * 4];
        float4 b = *(const float4*)&ks[c * 68 + tx * 4];
        float av[4] = {a.x, a.y, a.z, a.w};
        float bv[4] = {b.x, b.y, b.z, b.w};
        #pragma unroll
        for (int i = 0; i < 4; i++)
            #pragma unroll
            for (int j = 0; j < 4; j++) acc[i][j] += av[i] * bv[j];
    }
    #pragma unroll
    for (int i = 0; i < 4; i++) {
        float4 r = make_float4(acc[i][0], acc[i][1], acc[i][2], acc[i][3]);
        *(float4*)&g_Se[((size_t)h * NN + (n0 + ty * 4 + i)) * MM + m0 + tx * 4] = r;
    }
}

// ============================================================
// K4: fused RPE-score + softmax, depth-3 bulk-copy pipeline. (R10 exact)
// ============================================================
__global__ __launch_bounds__(256, 3) void attn_kernel(const float* __restrict__ emb,
                                                      float* __restrict__ attn_out)
{
    extern __shared__ __align__(16) float dyn[];
    float* sc  = dyn;                 // NH*MM floats (12 KB)
    float* buf = dyn + NH * MM;       // NBUF * 4096 floats (48 KB)

    const int n    = blockIdx.x;
    const int tid  = threadIdx.x;
    const int lane = tid & 31;
    const int wrp  = tid >> 5;

    __shared__ __align__(8) unsigned long long mbar[2 * NBUF];
    __shared__ float red[8];

    const uint32_t mb   = smem_u32(mbar);
    const uint32_t bufa = smem_u32(buf);

    if (tid == 0) {
        #pragma unroll
        for (int i = 0; i < NBUF; i++) {
            MB_INIT(mb + i * 8, 1);
            MB_INIT(mb + (NBUF + i) * 8, 8);
        }
    }

    #pragma unroll
    for (int h = 0; h < NH; h++)
        for (int m = tid; m < MM; m += 256)
            sc[h * MM + m] = g_Se[((size_t)h * NN + n) * MM + m];

    const float4* Rr = (const float4*)(g_R + (size_t)n * NH * DM);
    float4 rA[NH], rB[NH];
    #pragma unroll
    for (int h = 0; h < NH; h++) {
        rA[h] = Rr[h * 64 + lane];
        rB[h] = Rr[h * 64 + 32 + lane];
    }
    __syncthreads();

    const char* src = (const char*)(emb + (size_t)n * MM * DM);
    if (tid == 0) {
        #pragma unroll
        for (int i = 0; i < NBUF; i++) {
            MB_EXPECT_TX(mb + i * 8, TILE_BYTES);
            BULK_G2S(bufa + i * TILE_BYTES, src + (size_t)i * TILE_BYTES,
                     (uint32_t)TILE_BYTES, mb + i * 8);
        }
    }

    const unsigned F = 0xffffffffu;
    const bool o1 = lane & 1, o2 = lane & 2, o4 = lane & 4;

    int s = 0;
    uint32_t par = 0;
    for (int t = 0; t < NT; t++) {
        const uint32_t fa = mb + s * 8;
        const uint32_t ea = mb + (NBUF + s) * 8;

        mbar_wait(fa, par);

        const float* bufp = buf + s * TILE_FLOATS;
        const float4* r0p = (const float4*)(bufp + (wrp * 2) * DM);
        const float4* r1p = (const float4*)(bufp + (wrp * 2 + 1) * DM);
        float4 a0 = r0p[lane], a1 = r0p[32 + lane];
        float4 b0 = r1p[lane], b1 = r1p[32 + lane];

        float acc0[NH], acc1[NH];
        #pragma unroll
        for (int h = 0; h < NH; h++) {
            acc0[h] = a0.x * rA[h].x + a0.y * rA[h].y + a0.z * rA[h].z + a0.w * rA[h].w
                    + a1.x * rB[h].x + a1.y * rB[h].y + a1.z * rB[h].z + a1.w * rB[h].w;
            acc1[h] = b0.x * rA[h].x + b0.y * rA[h].y + b0.z * rA[h].z + b0.w * rA[h].w
                    + b1.x * rB[h].x + b1.y * rB[h].y + b1.z * rB[h].z + b1.w * rB[h].w;
        }

        float sx, rx;
        sx = o1 ? acc0[0] : acc0[1]; rx = __shfl_xor_sync(F, sx, 1);
        float v01a = (o1 ? acc0[1] : acc0[0]) + rx;
        sx = o1 ? acc0[2] : acc0[3]; rx = __shfl_xor_sync(F, sx, 1);
        float v23a = (o1 ? acc0[3] : acc0[2]) + rx;
        sx = o1 ? acc1[0] : acc1[1]; rx = __shfl_xor_sync(F, sx, 1);
        float v01b = (o1 ? acc1[1] : acc1[0]) + rx;
        sx = o1 ? acc1[2] : acc1[3]; rx = __shfl_xor_sync(F, sx, 1);
        float v23b = (o1 ? acc1[3] : acc1[2]) + rx;

        sx = o2 ? v01a : v23a; rx = __shfl_xor_sync(F, sx, 2);
        float ua = (o2 ? v23a : v01a) + rx;
        sx = o2 ? v01b : v23b; rx = __shfl_xor_sync(F, sx, 2);
        float ub = (o2 ? v23b : v01b) + rx;

        sx = o4 ? ua : ub; rx = __shfl_xor_sync(F, sx, 4);
        float w = (o4 ? ub : ua) + rx;
        w += __shfl_xor_sync(F, w, 8);
        w += __shfl_xor_sync(F, w, 16);

        if (lane < 8)
            sc[(lane & 3) * MM + t * TILE_M + wrp * 2 + ((lane >> 2) & 1)] += w;

        __syncwarp();
        if (lane == 0) MB_ARRIVE(ea);

        if (tid == 0 && t + NBUF < NT) {
            mbar_wait(ea, par);
            MB_EXPECT_TX(fa, TILE_BYTES);
            BULK_G2S(bufa + s * TILE_BYTES, src + (size_t)(t + NBUF) * TILE_BYTES,
                     (uint32_t)TILE_BYTES, fa);
        }

        if (++s == NBUF) { s = 0; par ^= 1; }
    }
    __syncthreads();

    const int h = tid >> 6;
    const int t = tid & 63;

    float mx = -1e30f;
    for (int m = t; m < MM; m += 64) mx = fmaxf(mx, sc[h * MM + m]);
    #pragma unroll
    for (int d = 16; d; d >>= 1) mx = fmaxf(mx, __shfl_xor_sync(0xffffffffu, mx, d));
    if (lane == 0) red[wrp] = mx;
    __syncthreads();
    const float hmax = fmaxf(red[h * 2], red[h * 2 + 1]);

    float sum = 0.f;
    for (int m = t; m < MM; m += 64) {
        float e = __expf(sc[h * MM + m] - hmax);
        sc[h * MM + m] = e;
        sum += e;
    }
    #pragma unroll
    for (int d = 16; d; d >>= 1) sum += __shfl_xor_sync(0xffffffffu, sum, d);
    __syncthreads();
    if (lane == 0) red[wrp] = sum;
    __syncthreads();
    const float inv = 1.0f / (red[h * 2] + red[h * 2 + 1]);

    float* ao = attn_out + ((size_t)h * NN + n) * MM;
    for (int m = t; m < MM; m += 64) ao[m] = sc[h * MM + m] * inv;
}

// ============================================================
// K5: hidden = attn @ v.  R10 ring structure, but 8 n-rows/block
// -> grid (96, 4) = 384 blocks (~2.6 CTAs/SM) so barrier drains in
// one CTA overlap compute in co-resident CTAs. 55 KB smem -> 4 CTAs/SM cap.
// warp = one n-row (attn LDS broadcast), lane = float2 of c.
// ============================================================
__global__ __launch_bounds__(256, 4) void av_kernel(const float* __restrict__ attn_g,
                                                    float* __restrict__ out_h)
{
    extern __shared__ __align__(16) float avs[];
    const int n0  = blockIdx.x * AV_ROWS;
    const int h   = blockIdx.y;
    const int tid = threadIdx.x;
    const int nl  = tid >> 5;        // warp id = row 0..7
    const int c2  = tid & 31;        // float2 col group

    auto issue = [&](int ph, int sb) {
        float* a_p = avs + sb * AV_BUF_FLOATS;
        float* v_p = a_p + AV_ROWS * AV_CH;
        const int m0 = ph * AV_CH;
        if (tid < 128) {   // attn[8][64]: 128 float4
            int r = tid >> 4, ch = tid & 15;
            cp_async16(a_p + r * 64 + ch * 4,
                       attn_g + ((size_t)h * NN + n0 + r) * MM + m0 + ch * 4);
        }
        #pragma unroll
        for (int i = 0; i < 4; i++) {  // v[64][64]: 1024 float4
            int j = tid + i * 256;
            int r = j >> 4, ch = j & 15;
            cp_async16(v_p + r * 64 + ch * 4,
                       g_v + (size_t)(m0 + r) * DM + h * 64 + ch * 4);
        }
        CP_COMMIT();
    };

    issue(0, 0);
    issue(1, 1);

    float2 acc = make_float2(0.f, 0.f);

    for (int ph = 0; ph < AV_PH; ph++) {
        const int sb = ph % 3;

        __syncthreads();   // all threads done with buffer being refilled
        if (ph + 2 < AV_PH) {
            issue(ph + 2, (ph + 2) % 3);
            CP_WAIT(2);
        } else if (ph + 1 < AV_PH) {
            CP_WAIT(1);
        } else {
            CP_WAIT(0);
        }
        __syncthreads();   // phase ph data visible

        const float* a_p = avs + sb * AV_BUF_FLOATS;
        const float* v_p = a_p + AV_ROWS * AV_CH;

        #pragma unroll
        for (int mm = 0; mm < AV_CH; mm += 4) {
            float4 a4 = *(const float4*)&a_p[nl * 64 + mm];      // warp broadcast
            float2 v0 = *(const float2*)&v_p[(mm + 0) * 64 + c2 * 2];
            float2 v1 = *(const float2*)&v_p[(mm + 1) * 64 + c2 * 2];
            float2 v2 = *(const float2*)&v_p[(mm + 2) * 64 + c2 * 2];
            float2 v3 = *(const float2*)&v_p[(mm + 3) * 64 + c2 * 2];
            acc.x += a4.x * v0.x + a4.y * v1.x + a4.z * v2.x + a4.w * v3.x;
            acc.y += a4.x * v0.y + a4.y * v1.y + a4.z * v2.y + a4.w * v3.y;
        }
    }

    *(float2*)(out_h + (size_t)(n0 + nl) * DM + h * 64 + c2 * 2) = acc;
}

// ============================================================
// launch
// ============================================================
extern "C" void kernel_launch(void* const* d_in, const int* in_sizes, int n_in,
                              void* d_out, int out_size)
{
    const float* in_q = (const float*)d_in[0];
    const float* in_k = (const float*)d_in[1];
    const float* in_v = (const float*)d_in[2];
    const float* emb  = (const float*)d_in[3];
    const float* Wq   = (const float*)d_in[4];
    const float* bq   = (const float*)d_in[5];
    const float* Wk   = (const float*)d_in[6];
    const float* bk   = (const float*)d_in[7];
    const float* Wv   = (const float*)d_in[8];
    const float* bv   = (const float*)d_in[9];
    const float* Wp   = (const float*)d_in[10];
    const float* bp   = (const float*)d_in[11];

    float* out      = (float*)d_out;
    float* out_attn = out + NN * DM;   // hidden (196608) then attn (2359296)

    static bool attr_set = false;
    if (!attr_set) {
        cudaFuncSetAttribute(attn_kernel, cudaFuncAttributeMaxDynamicSharedMemorySize,
                             DYN_SMEM_BYTES);
        cudaFuncSetAttribute(av_kernel, cudaFuncAttributeMaxDynamicSharedMemorySize,
                             AV_DYN_BYTES);
        attr_set = true;
    }

    qkv_kernel<<<dim3(NN / 16, 3), 256>>>(in_q, in_k, in_v, Wq, bq, Wk, bk, Wv, bv, bp);
    rproj_kernel<<<dim3(NN / 16, NH), 256>>>(Wp);
    se_kernel<<<dim3(MM / 64, NN / 64, NH), 256>>>();
    attn_kernel<<<NN, 256, DYN_SMEM_BYTES>>>(emb, out_attn);
    av_kernel<<<dim3(NN / AV_ROWS, NH), 256, AV_DYN_BYTES>>>(out_attn, out);
}

// round 17
// speedup vs baseline: 1.2060x; 1.0017x over previous
#include <cuda_runtime.h>
#include <math.h>
#include <stdint.h>

#define DM 256
#define NH 4
#define HD 64
#define NN 768
#define MM 768

#define TILE_M 16
#define NBUF 3
#define NT (MM / TILE_M)              // 48 tiles
#define TILE_BYTES (TILE_M * DM * 4)  // 16384
#define TILE_FLOATS (TILE_M * DM)     // 4096
#define DYN_SMEM_BYTES ((NH * MM + NBUF * TILE_FLOATS) * 4)   // 61440

// av kernel: 8 n-rows per block, per stage attn[8][64] + v[64][64]
#define AV_CH 64
#define AV_PH (MM / AV_CH)                            // 12 phases
#define AV_ROWS 8
#define AV_BUF_FLOATS (AV_ROWS * AV_CH + AV_CH * 64)  // 4608
#define AV_DYN_BYTES (3 * AV_BUF_FLOATS * 4)          // 55296

// ---- scratch (static device globals: allocation-free) ----
__device__ float g_q[NN * DM];
__device__ float g_k[NN * DM];            // k' = 0.125*(xk@Wk.T + bk + bp)
__device__ float g_v[NN * DM];
__device__ float g_R[NN * NH * DM];       // R[n][h][e] = 0.125 * q_h[n] @ Wp_h
__device__ float g_Se[NH * NN * MM];      // q·k' (scaled, bp folded)

// ---- mbarrier / bulk-copy / cp.async PTX helpers ----
__device__ __forceinline__ uint32_t smem_u32(const void* p) {
    return (uint32_t)__cvta_generic_to_shared(p);
}
#define MB_INIT(addr, cnt) \
    asm volatile("mbarrier.init.shared.b64 [%0], %1;" :: "r"(addr), "r"(cnt) : "memory")
#define MB_EXPECT_TX(addr, bytes) \
    asm volatile("mbarrier.arrive.expect_tx.shared.b64 _, [%0], %1;" :: "r"(addr), "r"(bytes) : "memory")
#define MB_ARRIVE(addr) \
    asm volatile("mbarrier.arrive.shared.b64 _, [%0];" :: "r"(addr) : "memory")
#define BULK_G2S(dst, src, bytes, mbar_) \
    asm volatile("cp.async.bulk.shared::cluster.global.mbarrier::complete_tx::bytes [%0], [%1], %2, [%3];" \
                 :: "r"(dst), "l"(src), "r"(bytes), "r"(mbar_) : "memory")

__device__ __forceinline__ void mbar_wait(uint32_t addr, uint32_t parity) {
    asm volatile(
        "{\n\t"
        ".reg .pred P;\n\t"
        "WL%=:\n\t"
        "mbarrier.try_wait.parity.acquire.cta.shared::cta.b64 P, [%0], %1, 0x989680;\n\t"
        "@P bra WD%=;\n\t"
        "bra WL%=;\n\t"
        "WD%=:\n\t"
        "}"
        :: "r"(addr), "r"(parity) : "memory");
}

__device__ __forceinline__ void cp_async16(float* dst, const float* src) {
    asm volatile("cp.async.ca.shared.global [%0], [%1], 16;"
                 :: "r"(smem_u32(dst)), "l"(src) : "memory");
}
#define CP_COMMIT() asm volatile("cp.async.commit_group;" ::: "memory")
#define CP_WAIT(n)  asm volatile("cp.async.wait_group %0;" :: "n"(n) : "memory")

// ============================================================
// K1: q/k'/v projections.  grid (48, 3), 256 threads.  (R16 exact)
// ============================================================
__global__ __launch_bounds__(256) void qkv_kernel(
    const float* __restrict__ in_q, const float* __restrict__ in_k, const float* __restrict__ in_v,
    const float* __restrict__ Wq, const float* __restrict__ bq,
    const float* __restrict__ Wk, const float* __restrict__ bk,
    const float* __restrict__ Wv, const float* __restrict__ bv,
    const float* __restrict__ bp)
{
    const int z  = blockIdx.y;
    const int n0 = blockIdx.x * 16;
    const int d  = threadIdx.x;

    const float* x = (z == 0) ? in_q : ((z == 1) ? in_k : in_v);
    const float* W = (z == 0) ? Wq   : ((z == 1) ? Wk   : Wv);
    float bias     = (z == 0) ? bq[d] : ((z == 1) ? (bk[d] + bp[d]) : bv[d]);
    const float scale = (z == 1) ? 0.125f : 1.0f;
    float* out = (z == 0) ? g_q : ((z == 1) ? g_k : g_v);

    __shared__ float xs[256 * 20];
    for (int idx = d; idx < 16 * 256; idx += 256) {
        int ni = idx >> 8, e = idx & 255;
        xs[e * 20 + ni] = x[(n0 + ni) * DM + e];
    }
    __syncthreads();

    float4 acc[4];
    #pragma unroll
    for (int g = 0; g < 4; g++) acc[g] = make_float4(0.f, 0.f, 0.f, 0.f);

    const float4* Wr = (const float4*)(W + d * DM);
    #pragma unroll 4
    for (int e4 = 0; e4 < 64; e4++) {
        float4 wv = Wr[e4];
        float wa[4] = {wv.x, wv.y, wv.z, wv.w};
        #pragma unroll
        for (int k = 0; k < 4; k++) {
            int e = e4 * 4 + k;
            float w = wa[k];
            #pragma unroll
            for (int g = 0; g < 4; g++) {
                float4 xf = *(const float4*)&xs[e * 20 + g * 4];
                acc[g].x += xf.x * w;
                acc[g].y += xf.y * w;
                acc[g].z += xf.z * w;
                acc[g].w += xf.w * w;
            }
        }
    }
    #pragma unroll
    for (int g = 0; g < 4; g++) {
        out[(n0 + g * 4 + 0) * DM + d] = scale * (acc[g].x + bias);
        out[(n0 + g * 4 + 1) * DM + d] = scale * (acc[g].y + bias);
        out[(n0 + g * 4 + 2) * DM + d] = scale * (acc[g].z + bias);
        out[(n0 + g * 4 + 3) * DM + d] = scale * (acc[g].w + bias);
    }
}

// ============================================================
// K2: R projection.  grid (48, 4), 256 threads.  (R16 exact)
// ============================================================
__global__ __launch_bounds__(256) void rproj_kernel(const float* __restrict__ Wp)
{
    const int n0 = blockIdx.x * 16;
    const int h  = blockIdx.y;
    const int e  = threadIdx.x;

    __shared__ float qs[64 * 20];
    for (int idx = e; idx < 16 * 64; idx += 256) {
        int ni = idx >> 6, c = idx & 63;
        qs[c * 20 + ni] = g_q[(n0 + ni) * DM + h * 64 + c];
    }
    __syncthreads();

    float4 acc[4];
    #pragma unroll
    for (int g = 0; g < 4; g++) acc[g] = make_float4(0.f, 0.f, 0.f, 0.f);

    #pragma unroll 4
    for (int c = 0; c < 64; c++) {
        float w = Wp[(h * 64 + c) * DM + e];
        #pragma unroll
        for (int g = 0; g < 4; g++) {
            float4 xf = *(const float4*)&qs[c * 20 + g * 4];
            acc[g].x += xf.x * w;
            acc[g].y += xf.y * w;
            acc[g].z += xf.z * w;
            acc[g].w += xf.w * w;
        }
    }
    #pragma unroll
    for (int g = 0; g < 4; g++) {
        g_R[(n0 + g * 4 + 0) * (NH * DM) + h * DM + e] = 0.125f * acc[g].x;
        g_R[(n0 + g * 4 + 1) * (NH * DM) + h * DM + e] = 0.125f * acc[g].y;
        g_R[(n0 + g * 4 + 2) * (NH * DM) + h * DM + e] = 0.125f * acc[g].z;
        g_R[(n0 + g * 4 + 3) * (NH * DM) + h * DM + e] = 0.125f * acc[g].w;
    }
}

// ============================================================
// K3: Se[h][n][m] = q_h[n] · k'_h[m].   grid (12, 12, 4), 256 threads.
// ============================================================
__global__ __launch_bounds__(256) void se_kernel()
{
    const int m0 = blockIdx.x * 64;
    const int n0 = blockIdx.y * 64;
    const int h  = blockIdx.z;
    const int tid = threadIdx.x;

    __shared__ float qs[64 * 68];
    __shared__ float ks[64 * 68];
    for (int idx = tid; idx < 64 * 64; idx += 256) {
        int i = idx >> 6, c = idx & 63;
        qs[c * 68 + i] = g_q[(n0 + i) * DM + h * 64 + c];
        ks[c * 68 + i] = g_k[(m0 + i) * DM + h * 64 + c];
    }
    __syncthreads();

    const int tx = tid & 15, ty = tid >> 4;
    float acc[4][4];
    #pragma unroll
    for (int i = 0; i < 4; i++)
        #pragma unroll
        for (int j = 0; j < 4; j++) acc[i][j] = 0.f;

    #pragma unroll 4
    for (int c = 0; c < 64; c++) {
        float4 a = *(const float4*)&qs[c * 68 + ty * 4];
        float4 b = *(const float4*)&ks[c * 68 + tx * 4];
        float av[4] = {a.x, a.y, a.z, a.w};
        float bv[4] = {b.x, b.y, b.z, b.w};
        #pragma unroll
        for (int i = 0; i < 4; i++)
            #pragma unroll
            for (int j = 0; j < 4; j++) acc[i][j] += av[i] * bv[j];
    }
    #pragma unroll
    for (int i = 0; i < 4; i++) {
        float4 r = make_float4(acc[i][0], acc[i][1], acc[i][2], acc[i][3]);
        *(float4*)&g_Se[((size_t)h * NN + (n0 + ty * 4 + i)) * MM + m0 + tx * 4] = r;
    }
}

// ============================================================
// K4: fused RPE-score + softmax — warp-specialized producer.
// grid 768, 288 threads (9 warps): warps 0-7 consume, warp 8 produces.
// Consumers never wait on each other; producer refills each buffer the
// moment its empty barrier fires. Same smem/regs budget (3 CTAs/SM).
// ============================================================
__global__ __launch_bounds__(288, 3) void attn_kernel(const float* __restrict__ emb,
                                                      float* __restrict__ attn_out)
{
    extern __shared__ __align__(16) float dyn[];
    float* sc  = dyn;                 // NH*MM floats (12 KB)
    float* buf = dyn + NH * MM;       // NBUF * 4096 floats (48 KB)

    const int n    = blockIdx.x;
    const int tid  = threadIdx.x;
    const int lane = tid & 31;
    const int wrp  = tid >> 5;        // 0..8

    __shared__ __align__(8) unsigned long long mbar[2 * NBUF];
    __shared__ float red[9];

    const uint32_t mb   = smem_u32(mbar);
    const uint32_t bufa = smem_u32(buf);

    if (tid == 0) {
        #pragma unroll
        for (int i = 0; i < NBUF; i++) {
            MB_INIT(mb + i * 8, 1);               // full[i]: TMA complete_tx
            MB_INIT(mb + (NBUF + i) * 8, 8);      // empty[i]: 8 consumer warps
        }
    }

    // Se init (288 threads) while barriers settle
    #pragma unroll
    for (int h = 0; h < NH; h++)
        for (int m = tid; m < MM; m += 288)
            sc[h * MM + m] = g_Se[((size_t)h * NN + n) * MM + m];

    // R fragments (consumer warps only need them; warp 8 loads harmlessly)
    const float4* Rr = (const float4*)(g_R + (size_t)n * NH * DM);
    float4 rA[NH], rB[NH];
    #pragma unroll
    for (int h = 0; h < NH; h++) {
        rA[h] = Rr[h * 64 + lane];
        rB[h] = Rr[h * 64 + 32 + lane];
    }
    __syncthreads();   // mbar init + sc visible to all 9 warps

    const char* src = (const char*)(emb + (size_t)n * MM * DM);
    const unsigned F = 0xffffffffu;

    if (wrp == 8) {
        // ---------------- producer warp ----------------
        if (lane == 0) {
            #pragma unroll
            for (int i = 0; i < NBUF; i++) {
                MB_EXPECT_TX(mb + i * 8, TILE_BYTES);
                BULK_G2S(bufa + i * TILE_BYTES, src + (size_t)i * TILE_BYTES,
                         (uint32_t)TILE_BYTES, mb + i * 8);
            }
            int s = 0;
            uint32_t par = 0;
            for (int t = 0; t + NBUF < NT; t++) {
                const uint32_t fa = mb + s * 8;
                const uint32_t ea = mb + (NBUF + s) * 8;
                mbar_wait(ea, par);            // all 8 consumers released buffer s
                MB_EXPECT_TX(fa, TILE_BYTES);
                BULK_G2S(bufa + s * TILE_BYTES, src + (size_t)(t + NBUF) * TILE_BYTES,
                         (uint32_t)TILE_BYTES, fa);
                if (++s == NBUF) { s = 0; par ^= 1; }
            }
        }
    } else {
        // ---------------- consumer warps 0..7 ----------------
        const bool o1 = lane & 1, o2 = lane & 2, o4 = lane & 4;
        int s = 0;
        uint32_t par = 0;
        for (int t = 0; t < NT; t++) {
            const uint32_t fa = mb + s * 8;
            const uint32_t ea = mb + (NBUF + s) * 8;

            mbar_wait(fa, par);

            const float* bufp = buf + s * TILE_FLOATS;
            const float4* r0p = (const float4*)(bufp + (wrp * 2) * DM);
            const float4* r1p = (const float4*)(bufp + (wrp * 2 + 1) * DM);
            float4 a0 = r0p[lane], a1 = r0p[32 + lane];
            float4 b0 = r1p[lane], b1 = r1p[32 + lane];

            float acc0[NH], acc1[NH];
            #pragma unroll
            for (int h = 0; h < NH; h++) {
                acc0[h] = a0.x * rA[h].x + a0.y * rA[h].y + a0.z * rA[h].z + a0.w * rA[h].w
                        + a1.x * rB[h].x + a1.y * rB[h].y + a1.z * rB[h].z + a1.w * rB[h].w;
                acc1[h] = b0.x * rA[h].x + b0.y * rA[h].y + b0.z * rA[h].z + b0.w * rA[h].w
                        + b1.x * rB[h].x + b1.y * rB[h].y + b1.z * rB[h].z + b1.w * rB[h].w;
            }

            float sx, rx;
            sx = o1 ? acc0[0] : acc0[1]; rx = __shfl_xor_sync(F, sx, 1);
            float v01a = (o1 ? acc0[1] : acc0[0]) + rx;
            sx = o1 ? acc0[2] : acc0[3]; rx = __shfl_xor_sync(F, sx, 1);
            float v23a = (o1 ? acc0[3] : acc0[2]) + rx;
            sx = o1 ? acc1[0] : acc1[1]; rx = __shfl_xor_sync(F, sx, 1);
            float v01b = (o1 ? acc1[1] : acc1[0]) + rx;
            sx = o1 ? acc1[2] : acc1[3]; rx = __shfl_xor_sync(F, sx, 1);
            float v23b = (o1 ? acc1[3] : acc1[2]) + rx;

            sx = o2 ? v01a : v23a; rx = __shfl_xor_sync(F, sx, 2);
            float ua = (o2 ? v23a : v01a) + rx;
            sx = o2 ? v01b : v23b; rx = __shfl_xor_sync(F, sx, 2);
            float ub = (o2 ? v23b : v01b) + rx;

            sx = o4 ? ua : ub; rx = __shfl_xor_sync(F, sx, 4);
            float w = (o4 ? ub : ua) + rx;
            w += __shfl_xor_sync(F, w, 8);
            w += __shfl_xor_sync(F, w, 16);

            if (lane < 8)
                sc[(lane & 3) * MM + t * TILE_M + wrp * 2 + ((lane >> 2) & 1)] += w;

            __syncwarp();
            if (lane == 0) MB_ARRIVE(ea);

            if (++s == NBUF) { s = 0; par ^= 1; }
        }
    }
    __syncthreads();   // all 9 warps

    // ---- softmax: warps 0..7 work (64 threads per head); warp 8 idles
    // through unconditionally-reached barriers ----
    const int h = tid >> 6;          // 0..3 valid for tid<256
    const int t = tid & 63;
    const bool act = (tid < 256);

    float mx = -1e30f;
    if (act)
        for (int m = t; m < MM; m += 64) mx = fmaxf(mx, sc[h * MM + m]);
    #pragma unroll
    for (int d = 16; d; d >>= 1) mx = fmaxf(mx, __shfl_xor_sync(F, mx, d));
    if (lane == 0) red[wrp] = mx;
    __syncthreads();
    const float hmax = act ? fmaxf(red[h * 2], red[h * 2 + 1]) : 0.f;

    float sum = 0.f;
    if (act) {
        for (int m = t; m < MM; m += 64) {
            float e = __expf(sc[h * MM + m] - hmax);
            sc[h * MM + m] = e;
            sum += e;
        }
    }
    #pragma unroll
    for (int d = 16; d; d >>= 1) sum += __shfl_xor_sync(F, sum, d);
    __syncthreads();
    if (lane == 0) red[wrp] = sum;
    __syncthreads();

    if (act) {
        const float inv = 1.0f / (red[h * 2] + red[h * 2 + 1]);
        float* ao = attn_out + ((size_t)h * NN + n) * MM;
        for (int m = t; m < MM; m += 64) ao[m] = sc[h * MM + m] * inv;
    }
}

// ============================================================
// K5: hidden = attn @ v.  (R16 exact — proven)
// ============================================================
__global__ __launch_bounds__(256, 4) void av_kernel(const float* __restrict__ attn_g,
                                                    float* __restrict__ out_h)
{
    extern __shared__ __align__(16) float avs[];
    const int n0  = blockIdx.x * AV_ROWS;
    const int h   = blockIdx.y;
    const int tid = threadIdx.x;
    const int nl  = tid >> 5;
    const int c2  = tid & 31;

    auto issue = [&](int ph, int sb) {
        float* a_p = avs + sb * AV_BUF_FLOATS;
        float* v_p = a_p + AV_ROWS * AV_CH;
        const int m0 = ph * AV_CH;
        if (tid < 128) {
            int r = tid >> 4, ch = tid & 15;
            cp_async16(a_p + r * 64 + ch * 4,
                       attn_g + ((size_t)h * NN + n0 + r) * MM + m0 + ch * 4);
        }
        #pragma unroll
        for (int i = 0; i < 4; i++) {
            int j = tid + i * 256;
            int r = j >> 4, ch = j & 15;
            cp_async16(v_p + r * 64 + ch * 4,
                       g_v + (size_t)(m0 + r) * DM + h * 64 + ch * 4);
        }
        CP_COMMIT();
    };

    issue(0, 0);
    issue(1, 1);

    float2 acc = make_float2(0.f, 0.f);

    for (int ph = 0; ph < AV_PH; ph++) {
        const int sb = ph % 3;

        __syncthreads();
        if (ph + 2 < AV_PH) {
            issue(ph + 2, (ph + 2) % 3);
            CP_WAIT(2);
        } else if (ph + 1 < AV_PH) {
            CP_WAIT(1);
        } else {
            CP_WAIT(0);
        }
        __syncthreads();

        const float* a_p = avs + sb * AV_BUF_FLOATS;
        const float* v_p = a_p + AV_ROWS * AV_CH;

        #pragma unroll
        for (int mm = 0; mm < AV_CH; mm += 4) {
            float4 a4 = *(const float4*)&a_p[nl * 64 + mm];
            float2 v0 = *(const float2*)&v_p[(mm + 0) * 64 + c2 * 2];
            float2 v1 = *(const float2*)&v_p[(mm + 1) * 64 + c2 * 2];
            float2 v2 = *(const float2*)&v_p[(mm + 2) * 64 + c2 * 2];
            float2 v3 = *(const float2*)&v_p[(mm + 3) * 64 + c2 * 2];
            acc.x += a4.x * v0.x + a4.y * v1.x + a4.z * v2.x + a4.w * v3.x;
            acc.y += a4.x * v0.y + a4.y * v1.y + a4.z * v2.y + a4.w * v3.y;
        }
    }

    *(float2*)(out_h + (size_t)(n0 + nl) * DM + h * 64 + c2 * 2) = acc;
}

// ============================================================
// launch
// ============================================================
extern "C" void kernel_launch(void* const* d_in, const int* in_sizes, int n_in,
                              void* d_out, int out_size)
{
    const float* in_q = (const float*)d_in[0];
    const float* in_k = (const float*)d_in[1];
    const float* in_v = (const float*)d_in[2];
    const float* emb  = (const float*)d_in[3];
    const float* Wq   = (const float*)d_in[4];
    const float* bq   = (const float*)d_in[5];
    const float* Wk   = (const float*)d_in[6];
    const float* bk   = (const float*)d_in[7];
    const float* Wv   = (const float*)d_in[8];
    const float* bv   = (const float*)d_in[9];
    const float* Wp   = (const float*)d_in[10];
    const float* bp   = (const float*)d_in[11];

    float* out      = (float*)d_out;
    float* out_attn = out + NN * DM;   // hidden (196608) then attn (2359296)

    static bool attr_set = false;
    if (!attr_set) {
        cudaFuncSetAttribute(attn_kernel, cudaFuncAttributeMaxDynamicSharedMemorySize,
                             DYN_SMEM_BYTES);
        cudaFuncSetAttribute(av_kernel, cudaFuncAttributeMaxDynamicSharedMemorySize,
                             AV_DYN_BYTES);
        attr_set = true;
    }

    qkv_kernel<<<dim3(NN / 16, 3), 256>>>(in_q, in_k, in_v, Wq, bq, Wk, bk, Wv, bv, bp);
    rproj_kernel<<<dim3(NN / 16, NH), 256>>>(Wp);
    se_kernel<<<dim3(MM / 64, NN / 64, NH), 256>>>();
    attn_kernel<<<NN, 288, DYN_SMEM_BYTES>>>(emb, out_attn);
    av_kernel<<<dim3(NN / AV_ROWS, NH), 256, AV_DYN_BYTES>>>(out_attn, out);
}